// round 14
// baseline (speedup 1.0000x reference)
#include <cuda_runtime.h>

#define FULLM 0xffffffffu
typedef unsigned long long ull;

namespace {
constexpr int NOUT = 32;
constexpr int KTOT = 288;   // 3*3*32
constexpr int BTOT = 576;   // 16*6*6
constexpr int NW   = 8;     // warps per block
constexpr int NK   = 36;    // k per warp, 1 per stage (k = warp + 8*st)
constexpr int NBUF = 4;     // cp.async ring depth
constexpr float EPSF = 1e-9f;
constexpr float LOG2PI = 1.8378770664093453f;
constexpr float LOG2E  = 1.4426950408889634f;
}

struct __align__(16) Smem {
    float pose[KTOT][16];        // 18 KB  im2col'd pose tile
    float act[KTOT];             //  1.1 KB
    union {
        char  wbuf[NBUF][NW][2048];  // 64 KB  staged w slices (mainloop)
        float red[NW][32][33];       // 33.8 KB per-warp partials (reduction)
    } u;
    float acc[NOUT][33];         // combined S1[16], S2[16], rsum
    float mu[NOUT][18];
    float is[NOUT][18];          // 0.5 / sigma2
    float L0[NOUT];
    float a[NOUT];
};

__device__ __forceinline__ ull pk2(float a, float b) {
    ull r; asm("mov.b64 %0,{%1,%2};" : "=l"(r) : "f"(a), "f"(b)); return r;
}
__device__ __forceinline__ void upk2(ull v, float& a, float& b) {
    asm("mov.b64 {%0,%1},%2;" : "=f"(a), "=f"(b) : "l"(v));
}
__device__ __forceinline__ ull fma2(ull a, ull b, ull c) {
    ull r; asm("fma.rn.f32x2 %0,%1,%2,%3;" : "=l"(r) : "l"(a), "l"(b), "l"(c)); return r;
}
__device__ __forceinline__ ull mul2(ull a, ull b) {
    ull r; asm("mul.rn.f32x2 %0,%1,%2;" : "=l"(r) : "l"(a), "l"(b)); return r;
}
__device__ __forceinline__ ull add2(ull a, ull b) {
    ull r; asm("add.rn.f32x2 %0,%1,%2;" : "=l"(r) : "l"(a), "l"(b)); return r;
}

// monotone key transform: float order -> s32 order (involution)
__device__ __forceinline__ int f2key(float x) {
    int i = __float_as_int(x);
    return i ^ ((i >> 31) & 0x7fffffff);
}
__device__ __forceinline__ float key2f(int k) {
    return __int_as_float(k ^ ((k >> 31) & 0x7fffffff));
}
__device__ __forceinline__ int redux_max_s32(int x) {
    int r; asm("redux.sync.max.s32 %0, %1, 0xffffffff;" : "=r"(r) : "r"(x));
    return r;
}
__device__ __forceinline__ int redux_add_s32(int x) {
    int r; asm("redux.sync.add.s32 %0, %1, 0xffffffff;" : "=r"(r) : "r"(x));
    return r;
}

__device__ __forceinline__ int sw2k(int b) {      // SW128 within a 2KB slice
    return b ^ ((b >> 3) & 0x70);
}

#define CP_COMMIT() asm volatile("cp.async.commit_group;")
#define CP_WAIT1()  asm volatile("cp.async.wait_group 1;")
#define CP_WAIT0()  asm volatile("cp.async.wait_group 0;")

// Stage one 2KB k-slice into wbuf[buf][warp] (4 x 16B per lane, coalesced).
__device__ __forceinline__ void stage_w1(unsigned wb_base,
                                         const float* __restrict__ w,
                                         int k, int lane, const unsigned swz[4],
                                         int buf)
{
    const float4* gsrc = reinterpret_cast<const float4*>(w + k * 512) + lane;
    unsigned b = wb_base + (unsigned)buf * (NW * 2048);
    #pragma unroll
    for (int j = 0; j < 4; j++) {
        asm volatile("cp.async.cg.shared.global [%0], [%1], 16;"
                     :: "r"(b + swz[j]), "l"(gsrc + j * 32));
    }
}

// Compute votes for capsule k from swizzled SMEM w-slice.
__device__ __forceinline__ void votes_k(const Smem& s, int k, const char* wk,
                                        const int wsw[4], ull v2[8])
{
    ull wpk[4][2];
    #pragma unroll
    for (int q = 0; q < 4; q++) {
        float4 f = *reinterpret_cast<const float4*>(wk + wsw[q]);
        wpk[q][0] = pk2(f.x, f.y);
        wpk[q][1] = pk2(f.z, f.w);
    }
    #pragma unroll
    for (int m = 0; m < 4; m++) {
        float4 pr = *(const float4*)&s.pose[k][m * 4];
        ull p0 = pk2(pr.x, pr.x), p1 = pk2(pr.y, pr.y);
        ull p2 = pk2(pr.z, pr.z), p3 = pk2(pr.w, pr.w);
        #pragma unroll
        for (int h = 0; h < 2; h++) {
            ull t = mul2(p3, wpk[3][h]);
            t = fma2(p2, wpk[2][h], t);
            t = fma2(p1, wpk[1][h], t);
            v2[m * 2 + h] = fma2(p0, wpk[0][h], t);
        }
    }
}

// logit (base-2) = L0eff - sum_d (A*v + B)*v, two 4-deep chains for ILP
__device__ __forceinline__ float logit2_of(const ull v2[8], const ull A2[8],
                                           const ull B2[8], float L0eff)
{
    ull lo = 0ull, hi = 0ull;
    #pragma unroll
    for (int i = 0; i < 4; i++) {
        ull ta = fma2(A2[i], v2[i], B2[i]);
        lo = fma2(ta, v2[i], lo);
        ull tb = fma2(A2[4 + i], v2[4 + i], B2[4 + i]);
        hi = fma2(tb, v2[4 + i], hi);
    }
    ull t = add2(lo, hi);
    float x, y; upk2(t, x, y);
    return L0eff - (x + y);
}

// Softmax weight for one vote set (s32-redux softmax) + accumulation.
template<int PASS>
__device__ __forceinline__ void proc_v(const Smem& s, int k, const ull v2[8],
                                       const ull A2[8], const ull B2[8],
                                       float L0eff,
                                       ull S1[8], ull S2[8], float& rsum)
{
    float rw;
    if (PASS == 0) {
        rw = s.act[k] * (1.f / 32.f);
    } else {
        float l = logit2_of(v2, A2, B2, L0eff);
        float mx = key2f(redux_max_s32(f2key(l)));
        // 2^25 scale folded into exponent; per-lane < 2^25, warp sum < 2^30.
        float e = exp2f(l - mx + 25.f);
        float sm = (float)redux_add_s32(__float2int_rn(e));
        rw = __fdividef(e, sm) * s.act[k];
    }
    rsum += rw;
    ull rw2 = pk2(rw, rw);
    #pragma unroll
    for (int i = 0; i < 8; i++) {
        ull t = mul2(rw2, v2[i]);
        S1[i] = add2(S1[i], t);
        S2[i] = fma2(t, v2[i], S2[i]);
    }
}

template<int PASS>
__device__ __forceinline__ void do_pass(Smem& s, const float* __restrict__ w,
                                        int tid, float inv_temp,
                                        float bv, float ba)
{
    const int warp = tid >> 5;
    const int o = tid & 31;

    // per-lane constants
    int wsw[4];
    unsigned swz[4];
    #pragma unroll
    for (int q = 0; q < 4; q++) {
        wsw[q] = sw2k((o * 4 + q) * 16);
        swz[q] = (unsigned)sw2k((q * 32 + o) * 16);
    }
    const unsigned wb_base =
        (unsigned)__cvta_generic_to_shared(&s.u.wbuf[0][warp][0]);
    const char* wkbase = &s.u.wbuf[0][warp][0];

    // E-step coefficients pre-scaled to base-2: A=0.5*log2e/s2, B=-mu*log2e/s2
    ull A2[8], B2[8];
    float L0eff = 0.f;
    if (PASS > 0) {
        float C = 0.f;
        #pragma unroll
        for (int i = 0; i < 8; i++) {
            float m0 = s.mu[o][2 * i], m1 = s.mu[o][2 * i + 1];
            float i0 = s.is[o][2 * i] * LOG2E, i1 = s.is[o][2 * i + 1] * LOG2E;
            A2[i] = pk2(i0, i1);
            B2[i] = pk2(-2.f * i0 * m0, -2.f * i1 * m1);
            C += i0 * m0 * m0 + i1 * m1 * m1;
        }
        L0eff = s.L0[o] * LOG2E - C;
    }

    ull S1[8], S2[8];
    #pragma unroll
    for (int i = 0; i < 8; i++) { S1[i] = 0ull; S2[i] = 0ull; }
    float rsum = 0.f;

    // ---- software-pipelined mainloop: votes one stage ahead ----
    // k(st) = warp + 8*st; buffer st & 3; staging runs two stages ahead.
    stage_w1(wb_base, w, warp, o, swz, 0); CP_COMMIT();
    stage_w1(wb_base, w, warp + NW, o, swz, 1); CP_COMMIT();
    CP_WAIT1(); __syncwarp();

    ull va[8], vb[8];
    votes_k(s, warp, wkbase, wsw, va);

    for (int st = 0; st < NK - 2; st += 2) {
        const int k0 = warp + NW * st;
        stage_w1(wb_base, w, k0 + 2 * NW, o, swz, (st + 2) & 3); CP_COMMIT();
        CP_WAIT1(); __syncwarp();
        votes_k(s, k0 + NW, wkbase + ((st + 1) & 3) * (NW * 2048), wsw, vb);
        proc_v<PASS>(s, k0, va, A2, B2, L0eff, S1, S2, rsum);

        stage_w1(wb_base, w, k0 + 3 * NW, o, swz, (st + 3) & 3); CP_COMMIT();
        CP_WAIT1(); __syncwarp();
        votes_k(s, k0 + 2 * NW, wkbase + ((st + 2) & 3) * (NW * 2048), wsw, va);
        proc_v<PASS>(s, k0 + NW, vb, A2, B2, L0eff, S1, S2, rsum);
    }
    // tail: st = NK-2; va holds votes(NK-2); stage NK-1 already staged.
    CP_WAIT0(); __syncwarp();
    votes_k(s, warp + NW * (NK - 1),
            wkbase + ((NK - 1) & 3) * (NW * 2048), wsw, vb);
    proc_v<PASS>(s, warp + NW * (NK - 2), va, A2, B2, L0eff, S1, S2, rsum);
    proc_v<PASS>(s, warp + NW * (NK - 1), vb, A2, B2, L0eff, S1, S2, rsum);

    // ---- cross-warp reduction: scatter partials, then owner-sum ----
    __syncthreads();          // all warps done with wbuf before red overlay
    {
        float* r = &s.u.red[warp][o][0];
        #pragma unroll
        for (int i = 0; i < 8; i++) {
            float x, y;
            upk2(S1[i], x, y);
            r[2 * i] = x; r[2 * i + 1] = y;
            upk2(S2[i], x, y);
            r[16 + 2 * i] = x; r[17 + 2 * i] = y;
        }
        r[32] = rsum;
    }
    __syncthreads();
    // warp g owns entries {g, g+8, g+16, g+24}; warp 0 also entry 32.
    #pragma unroll
    for (int j = 0; j < 4; j++) {
        int e = warp + 8 * j;
        float sum = 0.f;
        #pragma unroll
        for (int wi = 0; wi < NW; wi++) sum += s.u.red[wi][o][e];
        s.acc[o][e] = sum;
    }
    if (warp == 0) {
        float sum = 0.f;
        #pragma unroll
        for (int wi = 0; wi < NW; wi++) sum += s.u.red[wi][o][32];
        s.acc[o][32] = sum;
    }
    __syncthreads();

    // M-step epilogue: warp 0, lane = o
    if (tid < 32) {
        float rs = s.acc[o][32] + EPSF;
        float irs = 1.f / rs;
        float logsum = 0.f;
        #pragma unroll
        for (int d = 0; d < 16; d++) {
            float mu = s.acc[o][d] * irs;
            float sg = fmaxf(s.acc[o][16 + d] * irs - mu * mu, 0.f) + EPSF;
            s.mu[o][d] = mu;
            s.is[o][d] = 0.5f / sg;
            logsum += __logf(sg);
        }
        float costsum = (16.f * bv + 0.5f * logsum) * rs;
        float x = inv_temp * (ba - costsum);
        float a = 1.f / (1.f + __expf(-x));
        s.a[o] = a;
        s.L0[o] = __logf(a + EPSF) - 0.5f * (16.f * LOG2PI + logsum);
    }
    __syncthreads();
}

__global__ void __launch_bounds__(256, 2)
convcaps_kernel(const float* __restrict__ pose,
                const float* __restrict__ act,
                const float* __restrict__ w,
                const float* __restrict__ beta_v,
                const float* __restrict__ beta_a,
                float* __restrict__ out)
{
    extern __shared__ char smem_raw[];
    Smem& s = *reinterpret_cast<Smem*>(smem_raw);
    const int b = blockIdx.x;
    const int n = b / 36, rem = b % 36;
    const int h0 = (rem / 6) * 2, w0c = (rem % 6) * 2;
    const int tid = threadIdx.x;

    // im2col load of the 3x3x32 capsule neighborhood (poses float4 + acts)
    for (int idx = tid; idx < KTOT * 4; idx += 256) {
        int k = idx >> 2, q = idx & 3;
        int ki = k / 96, kj = (k >> 5) % 3, c = k & 31;
        const float4* src = reinterpret_cast<const float4*>(
            pose + ((((n * 14 + h0 + ki) * 14) + (w0c + kj)) * 32 + c) * 16) + q;
        *reinterpret_cast<float4*>(&s.pose[k][q * 4]) = *src;
    }
    for (int k = tid; k < KTOT; k += 256) {
        int ki = k / 96, kj = (k >> 5) % 3, c = k & 31;
        s.act[k] = act[((n * 14 + h0 + ki) * 14 + (w0c + kj)) * 32 + c];
    }
    __syncthreads();

    const int o = tid & 31;
    const float bv = beta_v[o];
    const float ba = beta_a[o];

    // 3 fused passes: M0, E0+M1, E1+M2  (inv_temp = 0.01*(1-0.95^(it+1)))
    do_pass<0>(s, w, tid, 0.0005f,     bv, ba);
    do_pass<1>(s, w, tid, 0.000975f,   bv, ba);
    do_pass<2>(s, w, tid, 0.00142625f, bv, ba);

    // outputs: pose (B,O,16) then activation (B,O)
    for (int idx = tid; idx < NOUT * 16; idx += 256)
        out[b * 512 + idx] = s.mu[idx >> 4][idx & 15];
    if (tid < 32)
        out[BTOT * 512 + b * 32 + tid] = s.a[tid];
}

extern "C" void kernel_launch(void* const* d_in, const int* in_sizes, int n_in,
                              void* d_out, int out_size) {
    const float* pose = (const float*)d_in[0];
    const float* act  = (const float*)d_in[1];
    const float* w    = (const float*)d_in[2];
    const float* bv   = (const float*)d_in[3];
    const float* ba   = (const float*)d_in[4];
    cudaFuncSetAttribute(convcaps_kernel,
                         cudaFuncAttributeMaxDynamicSharedMemorySize,
                         (int)sizeof(Smem));
    convcaps_kernel<<<BTOT, 256, sizeof(Smem)>>>(pose, act, w, bv, ba,
                                                 (float*)d_out);
}

// round 15
// speedup vs baseline: 1.0271x; 1.0271x over previous
#include <cuda_runtime.h>

#define FULLM 0xffffffffu
typedef unsigned long long ull;

namespace {
constexpr int NOUT = 32;
constexpr int KTOT = 288;   // 3*3*32
constexpr int BTOT = 576;   // 16*6*6
constexpr int NW   = 8;     // warps per block
constexpr int NSTEPS = 18;  // 36 k per warp, 2 k per stage
constexpr float EPSF = 1e-9f;
constexpr float LOG2PI = 1.8378770664093453f;
constexpr float LOG2E  = 1.4426950408889634f;
}

struct __align__(16) Smem {
    float2 pose2[KTOT][16];      // 36 KB  pose, each scalar duplicated {p,p}
    float act[KTOT];             //  1.1 KB
    union {
        char  wbuf[2][NW][2][2048];  // 64 KB  staged w slices (mainloop)
        float red[NW][32][33];       // 33.8 KB per-warp partials (reduction)
    } u;
    float acc[NOUT][33];         // combined S1[16], S2[16], rsum
    float mu[NOUT][18];
    float is[NOUT][18];          // 0.5 / sigma2
    float L0[NOUT];
    float a[NOUT];
};

__device__ __forceinline__ ull pk2(float a, float b) {
    ull r; asm("mov.b64 %0,{%1,%2};" : "=l"(r) : "f"(a), "f"(b)); return r;
}
__device__ __forceinline__ void upk2(ull v, float& a, float& b) {
    asm("mov.b64 {%0,%1},%2;" : "=f"(a), "=f"(b) : "l"(v));
}
__device__ __forceinline__ ull fma2(ull a, ull b, ull c) {
    ull r; asm("fma.rn.f32x2 %0,%1,%2,%3;" : "=l"(r) : "l"(a), "l"(b), "l"(c)); return r;
}
__device__ __forceinline__ ull mul2(ull a, ull b) {
    ull r; asm("mul.rn.f32x2 %0,%1,%2;" : "=l"(r) : "l"(a), "l"(b)); return r;
}
__device__ __forceinline__ ull add2(ull a, ull b) {
    ull r; asm("add.rn.f32x2 %0,%1,%2;" : "=l"(r) : "l"(a), "l"(b)); return r;
}

// monotone key transform: float order -> s32 order (involution)
__device__ __forceinline__ int f2key(float x) {
    int i = __float_as_int(x);
    return i ^ ((i >> 31) & 0x7fffffff);
}
__device__ __forceinline__ float key2f(int k) {
    return __int_as_float(k ^ ((k >> 31) & 0x7fffffff));
}
__device__ __forceinline__ int redux_max_s32(int x) {
    int r; asm("redux.sync.max.s32 %0, %1, 0xffffffff;" : "=r"(r) : "r"(x));
    return r;
}
__device__ __forceinline__ int redux_add_s32(int x) {
    int r; asm("redux.sync.add.s32 %0, %1, 0xffffffff;" : "=r"(r) : "r"(x));
    return r;
}

__device__ __forceinline__ int sw2k(int b) {      // SW128 within a 2KB slice
    return b ^ ((b >> 3) & 0x70);
}

// Stage the two k-slices (k = warp+16*st and +8) into wbuf[buf][warp][0/1].
__device__ __forceinline__ void stage_w(Smem& s, const float* __restrict__ w,
                                        int warp, int lane, int buf, int st)
{
    #pragma unroll
    for (int half = 0; half < 2; half++) {
        const int k = warp + 16 * st + 8 * half;
        const float4* gsrc = reinterpret_cast<const float4*>(w + k * 512);
        char* dst = s.u.wbuf[buf][warp][half];
        #pragma unroll
        for (int j = 0; j < 4; j++) {
            int unit = j * 32 + lane;                 // 16B unit, coalesced
            unsigned sa = (unsigned)__cvta_generic_to_shared(dst + sw2k(unit * 16));
            asm volatile("cp.async.cg.shared.global [%0], [%1], 16;"
                         :: "r"(sa), "l"(gsrc + unit));
        }
    }
}

// Compute votes for capsule k from swizzled SMEM w-slice; pose pairs come
// pre-duplicated from SMEM via LDS.128 (two {p,p} scalars per load): no MOVs.
__device__ __forceinline__ void votes_k(const Smem& s, int k, const char* wk,
                                        const int wsw[4], ull v2[8])
{
    ull wpk[4][2];
    #pragma unroll
    for (int q = 0; q < 4; q++) {
        float4 f = *reinterpret_cast<const float4*>(wk + wsw[q]);
        wpk[q][0] = pk2(f.x, f.y);
        wpk[q][1] = pk2(f.z, f.w);
    }
    const ulonglong2* pp = reinterpret_cast<const ulonglong2*>(&s.pose2[k][0]);
    #pragma unroll
    for (int m = 0; m < 4; m++) {
        ulonglong2 pa = pp[2 * m];        // {p0,p0},{p1,p1}
        ulonglong2 pb = pp[2 * m + 1];    // {p2,p2},{p3,p3}
        #pragma unroll
        for (int h = 0; h < 2; h++) {
            ull t = mul2(pb.y, wpk[3][h]);
            t = fma2(pb.x, wpk[2][h], t);
            t = fma2(pa.y, wpk[1][h], t);
            v2[m * 2 + h] = fma2(pa.x, wpk[0][h], t);
        }
    }
}

// logit (base-2) = L0eff - sum_d (A*v + B)*v, two 4-deep chains for ILP
__device__ __forceinline__ float logit2_of(const ull v2[8], const ull A2[8],
                                           const ull B2[8], float L0eff)
{
    ull lo = 0ull, hi = 0ull;
    #pragma unroll
    for (int i = 0; i < 4; i++) {
        ull ta = fma2(A2[i], v2[i], B2[i]);
        lo = fma2(ta, v2[i], lo);
        ull tb = fma2(A2[4 + i], v2[4 + i], B2[4 + i]);
        hi = fma2(tb, v2[4 + i], hi);
    }
    ull t = add2(lo, hi);
    float x, y; upk2(t, x, y);
    return L0eff - (x + y);
}

// One stage: two k's; softmax reductions via single-instruction s32 redux
// (max via monotone bit-key, sum via 2^25 fixed-point).
template<int PASS>
__device__ __forceinline__ void accum_stage(const Smem& s, int k0, int k1,
                                            const char* wk0, const char* wk1,
                                            const int wsw[4],
                                            const ull A2[8], const ull B2[8],
                                            float L0eff,
                                            ull S1[8], ull S2[8], float& rsum)
{
    ull v2a[8], v2b[8];
    votes_k(s, k0, wk0, wsw, v2a);
    votes_k(s, k1, wk1, wsw, v2b);

    float rwA, rwB;
    if (PASS == 0) {
        rwA = s.act[k0] * (1.f / 32.f);
        rwB = s.act[k1] * (1.f / 32.f);
    } else {
        float la = logit2_of(v2a, A2, B2, L0eff);
        float lb = logit2_of(v2b, A2, B2, L0eff);
        float mxa = key2f(redux_max_s32(f2key(la)));
        float mxb = key2f(redux_max_s32(f2key(lb)));
        // scale 2^25 folded into the exponent; per-lane value < 2^25,
        // warp sum < 2^30: no s32 overflow.
        float ea = exp2f(la - mxa + 25.f);
        float eb = exp2f(lb - mxb + 25.f);
        float sa = (float)redux_add_s32(__float2int_rn(ea));
        float sb = (float)redux_add_s32(__float2int_rn(eb));
        rwA = __fdividef(ea, sa) * s.act[k0];
        rwB = __fdividef(eb, sb) * s.act[k1];
    }

    rsum += rwA + rwB;
    ull rwA2 = pk2(rwA, rwA), rwB2 = pk2(rwB, rwB);
    #pragma unroll
    for (int i = 0; i < 8; i++) {
        ull ta = mul2(rwA2, v2a[i]);
        ull tb = mul2(rwB2, v2b[i]);
        S1[i] = add2(S1[i], add2(ta, tb));
        S2[i] = fma2(tb, v2b[i], fma2(ta, v2a[i], S2[i]));
    }
}

template<int PASS>
__device__ __forceinline__ void do_pass(Smem& s, const float* __restrict__ w,
                                        int tid, float inv_temp,
                                        float bv, float ba)
{
    const int warp = tid >> 5;
    const int o = tid & 31;

    // swizzled w offsets for this lane (constant across k)
    int wsw[4];
    #pragma unroll
    for (int q = 0; q < 4; q++) wsw[q] = sw2k((o * 4 + q) * 16);

    // E-step coefficients pre-scaled to base-2: A=0.5*log2e/s2, B=-mu*log2e/s2
    ull A2[8], B2[8];
    float L0eff = 0.f;
    if (PASS > 0) {
        float C = 0.f;
        #pragma unroll
        for (int i = 0; i < 8; i++) {
            float m0 = s.mu[o][2 * i], m1 = s.mu[o][2 * i + 1];
            float i0 = s.is[o][2 * i] * LOG2E, i1 = s.is[o][2 * i + 1] * LOG2E;
            A2[i] = pk2(i0, i1);
            B2[i] = pk2(-2.f * i0 * m0, -2.f * i1 * m1);
            C += i0 * m0 * m0 + i1 * m1 * m1;
        }
        L0eff = s.L0[o] * LOG2E - C;
    }

    ull S1[8], S2[8];
    #pragma unroll
    for (int i = 0; i < 8; i++) { S1[i] = 0ull; S2[i] = 0ull; }
    float rsum = 0.f;

    // per-warp double-buffered cp.async pipeline over the k stream
    stage_w(s, w, warp, o, 0, 0);
    asm volatile("cp.async.commit_group;");
    for (int st = 0; st < NSTEPS; st++) {
        if (st + 1 < NSTEPS)
            stage_w(s, w, warp, o, (st + 1) & 1, st + 1);
        asm volatile("cp.async.commit_group;");
        asm volatile("cp.async.wait_group 1;");
        __syncwarp();
        const int kbase = warp + 16 * st;
        accum_stage<PASS>(s, kbase, kbase + 8,
                          s.u.wbuf[st & 1][warp][0], s.u.wbuf[st & 1][warp][1],
                          wsw, A2, B2, L0eff, S1, S2, rsum);
    }

    // ---- cross-warp reduction: scatter partials, then owner-sum ----
    __syncthreads();          // all warps done reading wbuf before red overlay
    {
        float* r = &s.u.red[warp][o][0];
        #pragma unroll
        for (int i = 0; i < 8; i++) {
            float x, y;
            upk2(S1[i], x, y);
            r[2 * i] = x; r[2 * i + 1] = y;
            upk2(S2[i], x, y);
            r[16 + 2 * i] = x; r[17 + 2 * i] = y;
        }
        r[32] = rsum;
    }
    __syncthreads();
    // warp g owns entries {g, g+8, g+16, g+24}; warp 0 also entry 32.
    #pragma unroll
    for (int j = 0; j < 4; j++) {
        int e = warp + 8 * j;
        float sum = 0.f;
        #pragma unroll
        for (int wi = 0; wi < NW; wi++) sum += s.u.red[wi][o][e];
        s.acc[o][e] = sum;
    }
    if (warp == 0) {
        float sum = 0.f;
        #pragma unroll
        for (int wi = 0; wi < NW; wi++) sum += s.u.red[wi][o][32];
        s.acc[o][32] = sum;
    }
    __syncthreads();

    // M-step epilogue: warp 0, lane = o
    if (tid < 32) {
        float rs = s.acc[o][32] + EPSF;
        float irs = 1.f / rs;
        float logsum = 0.f;
        #pragma unroll
        for (int d = 0; d < 16; d++) {
            float mu = s.acc[o][d] * irs;
            float sg = fmaxf(s.acc[o][16 + d] * irs - mu * mu, 0.f) + EPSF;
            s.mu[o][d] = mu;
            s.is[o][d] = 0.5f / sg;
            logsum += __logf(sg);
        }
        float costsum = (16.f * bv + 0.5f * logsum) * rs;
        float x = inv_temp * (ba - costsum);
        float a = 1.f / (1.f + __expf(-x));
        s.a[o] = a;
        s.L0[o] = __logf(a + EPSF) - 0.5f * (16.f * LOG2PI + logsum);
    }
    __syncthreads();
}

__global__ void __launch_bounds__(256, 2)
convcaps_kernel(const float* __restrict__ pose,
                const float* __restrict__ act,
                const float* __restrict__ w,
                const float* __restrict__ beta_v,
                const float* __restrict__ beta_a,
                float* __restrict__ out)
{
    extern __shared__ char smem_raw[];
    Smem& s = *reinterpret_cast<Smem*>(smem_raw);
    const int b = blockIdx.x;
    const int n = b / 36, rem = b % 36;
    const int h0 = (rem / 6) * 2, w0c = (rem % 6) * 2;
    const int tid = threadIdx.x;

    // im2col load of the 3x3x32 neighborhood; pose written duplicated {p,p}
    for (int idx = tid; idx < KTOT * 4; idx += 256) {
        int k = idx >> 2, q = idx & 3;
        int ki = k / 96, kj = (k >> 5) % 3, c = k & 31;
        float4 v = *(reinterpret_cast<const float4*>(
            pose + ((((n * 14 + h0 + ki) * 14) + (w0c + kj)) * 32 + c) * 16) + q);
        s.pose2[k][q * 4 + 0] = make_float2(v.x, v.x);
        s.pose2[k][q * 4 + 1] = make_float2(v.y, v.y);
        s.pose2[k][q * 4 + 2] = make_float2(v.z, v.z);
        s.pose2[k][q * 4 + 3] = make_float2(v.w, v.w);
    }
    for (int k = tid; k < KTOT; k += 256) {
        int ki = k / 96, kj = (k >> 5) % 3, c = k & 31;
        s.act[k] = act[((n * 14 + h0 + ki) * 14 + (w0c + kj)) * 32 + c];
    }
    __syncthreads();

    const int o = tid & 31;
    const float bv = beta_v[o];
    const float ba = beta_a[o];

    // 3 fused passes: M0, E0+M1, E1+M2  (inv_temp = 0.01*(1-0.95^(it+1)))
    do_pass<0>(s, w, tid, 0.0005f,     bv, ba);
    do_pass<1>(s, w, tid, 0.000975f,   bv, ba);
    do_pass<2>(s, w, tid, 0.00142625f, bv, ba);

    // outputs: pose (B,O,16) then activation (B,O)
    for (int idx = tid; idx < NOUT * 16; idx += 256)
        out[b * 512 + idx] = s.mu[idx >> 4][idx & 15];
    if (tid < 32)
        out[BTOT * 512 + b * 32 + tid] = s.a[tid];
}

extern "C" void kernel_launch(void* const* d_in, const int* in_sizes, int n_in,
                              void* d_out, int out_size) {
    const float* pose = (const float*)d_in[0];
    const float* act  = (const float*)d_in[1];
    const float* w    = (const float*)d_in[2];
    const float* bv   = (const float*)d_in[3];
    const float* ba   = (const float*)d_in[4];
    cudaFuncSetAttribute(convcaps_kernel,
                         cudaFuncAttributeMaxDynamicSharedMemorySize,
                         (int)sizeof(Smem));
    convcaps_kernel<<<BTOT, 256, sizeof(Smem)>>>(pose, act, w, bv, ba,
                                                 (float*)d_out);
}

// round 17
// speedup vs baseline: 1.1178x; 1.0884x over previous
#include <cuda_runtime.h>

#define FULLM 0xffffffffu
typedef unsigned long long ull;

namespace {
constexpr int NOUT = 32;
constexpr int KTOT = 288;   // 3*3*32
constexpr int BTOT = 576;   // 16*6*6
constexpr int NW   = 8;     // warps per block
constexpr int NSTEPS = 18;  // 36 k per warp, 2 k per stage
constexpr float EPSF = 1e-9f;
constexpr float LOG2PI = 1.8378770664093453f;
constexpr float LOG2E  = 1.4426950408889634f;
}

struct __align__(16) Smem {
    float pose[KTOT][16];        // 18 KB  im2col'd pose tile
    float act[KTOT];             //  1.1 KB
    float bv[NOUT];
    float ba[NOUT];
    union {
        char  wbuf[2][NW][2][2048];  // 64 KB  staged w slices (mainloop)
        float red[NW][32][33];       // 33.8 KB per-warp partials (reduction)
    } u;
    float acc[NOUT][33];         // combined S1[16], S2[16], rsum
    float mu[NOUT][18];
    float is[NOUT][18];          // 0.5 / sigma2
    float L0[NOUT];
    float a[NOUT];
};

__device__ __forceinline__ ull pk2(float a, float b) {
    ull r; asm("mov.b64 %0,{%1,%2};" : "=l"(r) : "f"(a), "f"(b)); return r;
}
__device__ __forceinline__ void upk2(ull v, float& a, float& b) {
    asm("mov.b64 {%0,%1},%2;" : "=f"(a), "=f"(b) : "l"(v));
}
__device__ __forceinline__ ull fma2(ull a, ull b, ull c) {
    ull r; asm("fma.rn.f32x2 %0,%1,%2,%3;" : "=l"(r) : "l"(a), "l"(b), "l"(c)); return r;
}
__device__ __forceinline__ ull mul2(ull a, ull b) {
    ull r; asm("mul.rn.f32x2 %0,%1,%2;" : "=l"(r) : "l"(a), "l"(b)); return r;
}
__device__ __forceinline__ ull add2(ull a, ull b) {
    ull r; asm("add.rn.f32x2 %0,%1,%2;" : "=l"(r) : "l"(a), "l"(b)); return r;
}

// monotone key transform: float order -> s32 order (involution)
__device__ __forceinline__ int f2key(float x) {
    int i = __float_as_int(x);
    return i ^ ((i >> 31) & 0x7fffffff);
}
__device__ __forceinline__ float key2f(int k) {
    return __int_as_float(k ^ ((k >> 31) & 0x7fffffff));
}
__device__ __forceinline__ int redux_max_s32(int x) {
    int r; asm("redux.sync.max.s32 %0, %1, 0xffffffff;" : "=r"(r) : "r"(x));
    return r;
}
__device__ __forceinline__ int redux_add_s32(int x) {
    int r; asm("redux.sync.add.s32 %0, %1, 0xffffffff;" : "=r"(r) : "r"(x));
    return r;
}

__device__ __forceinline__ int sw2k(int b) {      // SW128 within a 2KB slice
    return b ^ ((b >> 3) & 0x70);
}

// Stage the two k-slices (k = warp+16*st and +8) into wbuf[buf][warp][0/1].
__device__ __forceinline__ void stage_w(Smem& s, const float* __restrict__ w,
                                        int warp, int lane, int buf, int st)
{
    #pragma unroll
    for (int half = 0; half < 2; half++) {
        const int k = warp + 16 * st + 8 * half;
        const float4* gsrc = reinterpret_cast<const float4*>(w + k * 512);
        char* dst = s.u.wbuf[buf][warp][half];
        #pragma unroll
        for (int j = 0; j < 4; j++) {
            int unit = j * 32 + lane;                 // 16B unit, coalesced
            unsigned sa = (unsigned)__cvta_generic_to_shared(dst + sw2k(unit * 16));
            asm volatile("cp.async.cg.shared.global [%0], [%1], 16;"
                         :: "r"(sa), "l"(gsrc + unit));
        }
    }
}

// Compute votes for capsule k from swizzled SMEM w-slice.
__device__ __forceinline__ void votes_k(const Smem& s, int k, const char* wk,
                                        const int wsw[4], ull v2[8])
{
    ull wpk[4][2];
    #pragma unroll
    for (int q = 0; q < 4; q++) {
        float4 f = *reinterpret_cast<const float4*>(wk + wsw[q]);
        wpk[q][0] = pk2(f.x, f.y);
        wpk[q][1] = pk2(f.z, f.w);
    }
    #pragma unroll
    for (int m = 0; m < 4; m++) {
        float4 pr = *(const float4*)&s.pose[k][m * 4];
        ull p0 = pk2(pr.x, pr.x), p1 = pk2(pr.y, pr.y);
        ull p2 = pk2(pr.z, pr.z), p3 = pk2(pr.w, pr.w);
        #pragma unroll
        for (int h = 0; h < 2; h++) {
            ull t = mul2(p3, wpk[3][h]);
            t = fma2(p2, wpk[2][h], t);
            t = fma2(p1, wpk[1][h], t);
            v2[m * 2 + h] = fma2(p0, wpk[0][h], t);
        }
    }
}

// logit (base-2) = L0eff - sum_d (A*v + B)*v, two 4-deep chains for ILP
__device__ __forceinline__ float logit2_of(const ull v2[8], const ull A2[8],
                                           const ull B2[8], float L0eff)
{
    ull lo = 0ull, hi = 0ull;
    #pragma unroll
    for (int i = 0; i < 4; i++) {
        ull ta = fma2(A2[i], v2[i], B2[i]);
        lo = fma2(ta, v2[i], lo);
        ull tb = fma2(A2[4 + i], v2[4 + i], B2[4 + i]);
        hi = fma2(tb, v2[4 + i], hi);
    }
    ull t = add2(lo, hi);
    float x, y; upk2(t, x, y);
    return L0eff - (x + y);
}

// One stage: two k's; softmax reductions via single-instruction s32 redux.
template<int PASS>
__device__ __forceinline__ void accum_stage(const Smem& s, int k0, int k1,
                                            const char* wk0, const char* wk1,
                                            const int wsw[4],
                                            const ull A2[8], const ull B2[8],
                                            float L0eff,
                                            ull S1[8], ull S2[8], float& rsum)
{
    ull v2a[8], v2b[8];
    votes_k(s, k0, wk0, wsw, v2a);
    votes_k(s, k1, wk1, wsw, v2b);

    float rwA, rwB;
    if (PASS == 0) {
        rwA = s.act[k0] * (1.f / 32.f);
        rwB = s.act[k1] * (1.f / 32.f);
    } else {
        float la = logit2_of(v2a, A2, B2, L0eff);
        float lb = logit2_of(v2b, A2, B2, L0eff);
        float mxa = key2f(redux_max_s32(f2key(la)));
        float mxb = key2f(redux_max_s32(f2key(lb)));
        float ea = exp2f(la - mxa + 25.f);
        float eb = exp2f(lb - mxb + 25.f);
        float sa = (float)redux_add_s32(__float2int_rn(ea));
        float sb = (float)redux_add_s32(__float2int_rn(eb));
        rwA = __fdividef(ea, sa) * s.act[k0];
        rwB = __fdividef(eb, sb) * s.act[k1];
    }

    rsum += rwA + rwB;
    ull rwA2 = pk2(rwA, rwA), rwB2 = pk2(rwB, rwB);
    #pragma unroll
    for (int i = 0; i < 8; i++) {
        ull ta = mul2(rwA2, v2a[i]);
        ull tb = mul2(rwB2, v2b[i]);
        S1[i] = add2(S1[i], add2(ta, tb));
        S2[i] = fma2(tb, v2b[i], fma2(ta, v2a[i], S2[i]));
    }
}

template<int PASS>
__device__ __forceinline__ void do_pass(Smem& s, const float* __restrict__ w,
                                        int tid, float inv_temp)
{
    const int warp = tid >> 5;
    const int o = tid & 31;

    int wsw[4];
    #pragma unroll
    for (int q = 0; q < 4; q++) wsw[q] = sw2k((o * 4 + q) * 16);

    // E-step coefficients pre-scaled to base-2
    ull A2[8], B2[8];
    float L0eff = 0.f;
    if (PASS > 0) {
        float C = 0.f;
        #pragma unroll
        for (int i = 0; i < 8; i++) {
            float m0 = s.mu[o][2 * i], m1 = s.mu[o][2 * i + 1];
            float i0 = s.is[o][2 * i] * LOG2E, i1 = s.is[o][2 * i + 1] * LOG2E;
            A2[i] = pk2(i0, i1);
            B2[i] = pk2(-2.f * i0 * m0, -2.f * i1 * m1);
            C += i0 * m0 * m0 + i1 * m1 * m1;
        }
        L0eff = s.L0[o] * LOG2E - C;
    }

    ull S1[8], S2[8];
    #pragma unroll
    for (int i = 0; i < 8; i++) { S1[i] = 0ull; S2[i] = 0ull; }
    float rsum = 0.f;

    // per-warp double-buffered cp.async pipeline over the k stream
    stage_w(s, w, warp, o, 0, 0);
    asm volatile("cp.async.commit_group;");
    #pragma unroll 2
    for (int st = 0; st < NSTEPS; st++) {
        if (st + 1 < NSTEPS)
            stage_w(s, w, warp, o, (st + 1) & 1, st + 1);
        asm volatile("cp.async.commit_group;");
        asm volatile("cp.async.wait_group 1;");
        __syncwarp();
        const int kbase = warp + 16 * st;
        accum_stage<PASS>(s, kbase, kbase + 8,
                          s.u.wbuf[st & 1][warp][0], s.u.wbuf[st & 1][warp][1],
                          wsw, A2, B2, L0eff, S1, S2, rsum);
    }

    // ---- cross-warp reduction: scatter partials, then owner-sum ----
    __syncthreads();
    {
        float* r = &s.u.red[warp][o][0];
        #pragma unroll
        for (int i = 0; i < 8; i++) {
            float x, y;
            upk2(S1[i], x, y);
            r[2 * i] = x; r[2 * i + 1] = y;
            upk2(S2[i], x, y);
            r[16 + 2 * i] = x; r[17 + 2 * i] = y;
        }
        r[32] = rsum;
    }
    __syncthreads();
    #pragma unroll
    for (int j = 0; j < 4; j++) {
        int e = warp + 8 * j;
        float sum = 0.f;
        #pragma unroll
        for (int wi = 0; wi < NW; wi++) sum += s.u.red[wi][o][e];
        s.acc[o][e] = sum;
    }
    if (warp == 0) {
        float sum = 0.f;
        #pragma unroll
        for (int wi = 0; wi < NW; wi++) sum += s.u.red[wi][o][32];
        s.acc[o][32] = sum;
    }
    __syncthreads();

    // ---- M-step epilogue: parallel over all 256 threads ----
    // thread -> (om = tid>>3, jj = tid&7) handles d = 2*jj, 2*jj+1.
    {
        const int om = tid >> 3;
        const int jj = tid & 7;
        const int d0 = 2 * jj;
        float rs = s.acc[om][32] + EPSF;
        float irs = 1.f / rs;
        float mu0 = s.acc[om][d0] * irs;
        float mu1 = s.acc[om][d0 + 1] * irs;
        float sg0 = fmaxf(s.acc[om][16 + d0] * irs - mu0 * mu0, 0.f) + EPSF;
        float sg1 = fmaxf(s.acc[om][17 + d0] * irs - mu1 * mu1, 0.f) + EPSF;
        float logsum = __logf(sg0) + __logf(sg1);
        // segmented butterfly over the 8-lane group
        logsum += __shfl_xor_sync(FULLM, logsum, 1);
        logsum += __shfl_xor_sync(FULLM, logsum, 2);
        logsum += __shfl_xor_sync(FULLM, logsum, 4);
        s.mu[om][d0] = mu0;
        s.mu[om][d0 + 1] = mu1;
        s.is[om][d0] = 0.5f / sg0;
        s.is[om][d0 + 1] = 0.5f / sg1;
        if (jj == 0) {
            float costsum = (16.f * s.bv[om] + 0.5f * logsum) * rs;
            float x = inv_temp * (s.ba[om] - costsum);
            float a = 1.f / (1.f + __expf(-x));
            s.a[om] = a;
            s.L0[om] = __logf(a + EPSF) - 0.5f * (16.f * LOG2PI + logsum);
        }
    }
    __syncthreads();
}

__global__ void __launch_bounds__(256, 2)
convcaps_kernel(const float* __restrict__ pose,
                const float* __restrict__ act,
                const float* __restrict__ w,
                const float* __restrict__ beta_v,
                const float* __restrict__ beta_a,
                float* __restrict__ out)
{
    extern __shared__ char smem_raw[];
    Smem& s = *reinterpret_cast<Smem*>(smem_raw);
    const int b = blockIdx.x;
    const int n = b / 36, rem = b % 36;
    const int h0 = (rem / 6) * 2, w0c = (rem % 6) * 2;
    const int tid = threadIdx.x;

    // im2col load of the 3x3x32 capsule neighborhood (poses float4 + acts)
    for (int idx = tid; idx < KTOT * 4; idx += 256) {
        int k = idx >> 2, q = idx & 3;
        int ki = k / 96, kj = (k >> 5) % 3, c = k & 31;
        const float4* src = reinterpret_cast<const float4*>(
            pose + ((((n * 14 + h0 + ki) * 14) + (w0c + kj)) * 32 + c) * 16) + q;
        *reinterpret_cast<float4*>(&s.pose[k][q * 4]) = *src;
    }
    for (int k = tid; k < KTOT; k += 256) {
        int ki = k / 96, kj = (k >> 5) % 3, c = k & 31;
        s.act[k] = act[((n * 14 + h0 + ki) * 14 + (w0c + kj)) * 32 + c];
    }
    if (tid < NOUT) {
        s.bv[tid] = beta_v[tid];
        s.ba[tid] = beta_a[tid];
    }
    __syncthreads();

    // 3 fused passes: M0, E0+M1, E1+M2  (inv_temp = 0.01*(1-0.95^(it+1)))
    do_pass<0>(s, w, tid, 0.0005f);
    do_pass<1>(s, w, tid, 0.000975f);
    do_pass<2>(s, w, tid, 0.00142625f);

    // outputs: pose (B,O,16) then activation (B,O)
    for (int idx = tid; idx < NOUT * 16; idx += 256)
        out[b * 512 + idx] = s.mu[idx >> 4][idx & 15];
    if (tid < 32)
        out[BTOT * 512 + b * 32 + tid] = s.a[tid];
}

extern "C" void kernel_launch(void* const* d_in, const int* in_sizes, int n_in,
                              void* d_out, int out_size) {
    const float* pose = (const float*)d_in[0];
    const float* act  = (const float*)d_in[1];
    const float* w    = (const float*)d_in[2];
    const float* bv   = (const float*)d_in[3];
    const float* ba   = (const float*)d_in[4];
    cudaFuncSetAttribute(convcaps_kernel,
                         cudaFuncAttributeMaxDynamicSharedMemorySize,
                         (int)sizeof(Smem));
    convcaps_kernel<<<BTOT, 256, sizeof(Smem)>>>(pose, act, w, bv, ba,
                                                 (float*)d_out);
}